// round 9
// baseline (speedup 1.0000x reference)
#include <cuda_runtime.h>
#include <cuda_bf16.h>

// Problem constants (match reference)
#define D_DIM 64
#define LA_N  20
#define LC_N  5

__global__ void __launch_bounds__(256)
aspect_kernel(const int* __restrict__ user_id,
              const int* __restrict__ artists_id,
              const int* __restrict__ categories_id,
              const float* __restrict__ user_factors,
              const float* __restrict__ entity_factors,
              const float* __restrict__ relation_k,
              float* __restrict__ out,
              int B)
{
    const int warp = (blockIdx.x * blockDim.x + threadIdx.x) >> 5;
    const int lane = threadIdx.x & 31;
    if (warp >= B) return;

    const int uid = user_id[warp];
    // Each lane owns 2 consecutive dims of the user vector (coalesced 256B row).
    const float2 u = *reinterpret_cast<const float2*>(
        user_factors + (size_t)uid * D_DIM + lane * 2);

    // ---- relation logits: u @ relation_k (relation_k is [D, 3] row-major) ----
    const int d0 = lane * 2;
    const float* rk0 = relation_k + d0 * 3;
    float l0 = u.x * rk0[0] + u.y * rk0[3];
    float l1 = u.x * rk0[1] + u.y * rk0[4];
    float l2 = u.x * rk0[2] + u.y * rk0[5];
    #pragma unroll
    for (int s = 16; s > 0; s >>= 1) {
        l0 += __shfl_xor_sync(0xffffffffu, l0, s);
        l1 += __shfl_xor_sync(0xffffffffu, l1, s);
        l2 += __shfl_xor_sync(0xffffffffu, l2, s);
    }
    // leaky_relu(0.2) then softmax over 3 (all lanes redundantly)
    l0 = (l0 > 0.f) ? l0 : 0.2f * l0;
    l1 = (l1 > 0.f) ? l1 : 0.2f * l1;
    l2 = (l2 > 0.f) ? l2 : 0.2f * l2;
    const float m  = fmaxf(l0, fmaxf(l1, l2));
    const float e0 = __expf(l0 - m);
    const float e1 = __expf(l1 - m);
    const float e2 = __expf(l2 - m);
    const float inv = 1.f / (e0 + e1 + e2);
    const float s_act = e0 * inv;
    const float s_dir = e1 * inv;
    const float s_2   = e2 * inv;

    // ---- artists: 20 gathered 64-dots ----
    // Load indices once (lanes 0..19), broadcast per iteration.
    int myIdxA = (lane < LA_N) ? artists_id[warp * LA_N + lane] : 0;
    float preA = 0.f;   // lane l keeps entity l's dot
    float sumA = 0.f;
    #pragma unroll
    for (int l = 0; l < LA_N; ++l) {
        const int e = __shfl_sync(0xffffffffu, myIdxA, l);
        const float2 v = *reinterpret_cast<const float2*>(
            entity_factors + (size_t)e * D_DIM + lane * 2);
        float d = v.x * u.x + v.y * u.y;
        #pragma unroll
        for (int s = 16; s > 0; s >>= 1)
            d += __shfl_xor_sync(0xffffffffu, d, s);
        sumA += d;
        if (lane == l) preA = d;
    }
    const float c_act = sumA * (1.f / LA_N);

    // ---- categories: 5 gathered 64-dots ----
    int myIdxC = (lane < LC_N) ? categories_id[warp * LC_N + lane] : 0;
    float preC = 0.f;
    float sumC = 0.f;
    #pragma unroll
    for (int l = 0; l < LC_N; ++l) {
        const int e = __shfl_sync(0xffffffffu, myIdxC, l);
        const float2 v = *reinterpret_cast<const float2*>(
            entity_factors + (size_t)e * D_DIM + lane * 2);
        float d = v.x * u.x + v.y * u.y;
        #pragma unroll
        for (int s = 16; s > 0; s >>= 1)
            d += __shfl_xor_sync(0xffffffffu, d, s);
        sumC += d;
        if (lane == l) preC = d;
    }
    const float c_dir = sumC * (1.f / LC_N);

    const float prediction = (c_act * s_act + c_dir * s_dir) / (s_act + s_dir);

    // ---- outputs: prediction[B] | scores[B,3] | c_act[B] | c_dir[B] |
    //               niubi_act[B,20] | niubi_dir[B,5]
    float* o_pred  = out;
    float* o_score = out + (size_t)B;
    float* o_cact  = out + (size_t)4 * B;
    float* o_cdir  = out + (size_t)5 * B;
    float* o_na    = out + (size_t)6 * B;
    float* o_nd    = out + (size_t)26 * B;

    if (lane == 0) {
        o_pred[warp] = prediction;
        o_cact[warp] = c_act;
        o_cdir[warp] = c_dir;
    }
    if (lane < 3) {
        const float sc = (lane == 0) ? s_act : (lane == 1) ? s_dir : s_2;
        o_score[warp * 3 + lane] = sc;
    }
    if (lane < LA_N) o_na[warp * LA_N + lane] = preA;
    if (lane < LC_N) o_nd[warp * LC_N + lane] = preC;
}

extern "C" void kernel_launch(void* const* d_in, const int* in_sizes, int n_in,
                              void* d_out, int out_size)
{
    // Input order: user_id, artists_id, categories_id, [rate], user_factors,
    //              entity_factors, relation_k. 'rate' is a python scalar and
    //              may or may not materialize as a buffer.
    int iU = 0, iA = 1, iC = 2, iUF, iEF, iRK;
    if (n_in >= 7) { iUF = 4; iEF = 5; iRK = 6; }
    else           { iUF = 3; iEF = 4; iRK = 5; }

    const int* user_id       = (const int*)d_in[iU];
    const int* artists_id    = (const int*)d_in[iA];
    const int* categories_id = (const int*)d_in[iC];
    const float* user_factors   = (const float*)d_in[iUF];
    const float* entity_factors = (const float*)d_in[iEF];
    const float* relation_k     = (const float*)d_in[iRK];
    float* out = (float*)d_out;

    const int B = in_sizes[iU];           // 16384
    const int warps_per_block = 8;        // 256 threads
    const int grid = (B + warps_per_block - 1) / warps_per_block;

    aspect_kernel<<<grid, warps_per_block * 32>>>(
        user_id, artists_id, categories_id,
        user_factors, entity_factors, relation_k, out, B);
}